// round 13
// baseline (speedup 1.0000x reference)
#include <cuda_runtime.h>
#include <cuda_bf16.h>
#include <cstdint>

// ---------------- problem constants ----------------
#define TSEQ 2048
#define TD   64
#define TDK  128            // combined head dim [Q|Qpos]
#define BQ   128            // q rows per CTA
#define BK   64             // kv rows per tile
#define NT   256            // 8 warps
#define NTILES (TSEQ/BK)    // 32

// ---------------- SMEM (bytes, dynamic), TRIPLE buffered ----------------
// per buffer: KH [64][136]bf16 @0, KL @17408, VH [64][72]bf16 @34816, VL @44032
#define KPITCH 272
#define VPITCH 144
#define SM_KH 0
#define SM_KL 17408
#define SM_VH 34816
#define SM_VL 44032
#define BUFSZ 53248
#define SMEM_TOTAL (3*BUFSZ)          // 159,744 B
// Q staging (prologue only, overlaps buffers): hi @0, lo @34816
#define SM_QH 0
#define SM_QL 34816

__device__ __forceinline__ uint32_t smem_u32(const void* p) {
    uint32_t a;
    asm("{ .reg .u64 t; cvta.to.shared.u64 t, %1; cvt.u32.u64 %0, t; }" : "=r"(a) : "l"(p));
    return a;
}
__device__ __forceinline__ uint32_t cvt2bf(float e1, float e0) {
    uint32_t r;
    asm("cvt.rn.bf16x2.f32 %0, %1, %2;" : "=r"(r) : "f"(e1), "f"(e0));
    return r;
}
__device__ __forceinline__ float ex2(float x) {
    float y;
    asm("ex2.approx.f32 %0, %1;" : "=f"(y) : "f"(x));
    return y;
}

#define HMMA(d, a, b0, b1)                                                       \
    asm volatile("mma.sync.aligned.m16n8k16.row.col.f32.bf16.bf16.f32 "          \
        "{%0,%1,%2,%3}, {%4,%5,%6,%7}, {%8,%9}, {%0,%1,%2,%3};"                  \
        : "+f"((d)[0]), "+f"((d)[1]), "+f"((d)[2]), "+f"((d)[3])                 \
        : "r"((a)[0]), "r"((a)[1]), "r"((a)[2]), "r"((a)[3]), "r"(b0), "r"(b1))

#define LDSM4(r0, r1, r2, r3, addr)                                              \
    asm volatile("ldmatrix.sync.aligned.m8n8.x4.shared.b16 {%0,%1,%2,%3}, [%4];" \
        : "=r"(r0), "=r"(r1), "=r"(r2), "=r"(r3) : "r"(addr))

#define LDSM4T(r0, r1, r2, r3, addr)                                             \
    asm volatile("ldmatrix.sync.aligned.m8n8.x4.trans.shared.b16 {%0,%1,%2,%3}, [%4];" \
        : "=r"(r0), "=r"(r1), "=r"(r2), "=r"(r3) : "r"(addr))

__device__ __forceinline__ void split_store(char* sm, uint32_t off_h, uint32_t off_l,
                                            float4 v) {
    uint32_t h01 = cvt2bf(v.y, v.x);
    uint32_t h23 = cvt2bf(v.w, v.z);
    float r0 = v.x - __uint_as_float(h01 << 16);
    float r1 = v.y - __uint_as_float(h01 & 0xFFFF0000u);
    float r2 = v.z - __uint_as_float(h23 << 16);
    float r3 = v.w - __uint_as_float(h23 & 0xFFFF0000u);
    *(uint2*)(sm + off_h) = make_uint2(h01, h23);
    *(uint2*)(sm + off_l) = make_uint2(cvt2bf(r1, r0), cvt2bf(r3, r2));
}

// ---- one QK k-chunk: 8 LDSM4 + 18 HMMA into SN, reading K buffer at BOFF ----
#define QK_STEP(kk, SN, BOFF) {                                                  \
    _Pragma("unroll")                                                            \
    for (int np_ = 0; np_ < 4; np_++) {                                          \
        uint32_t off_ = (BOFF) + (16u*np_ + k_row)*KPITCH + (uint32_t)(kk)*32 + k_kseg; \
        uint32_t h0_,h1_,h2_,h3_,e0_,e1_,e2_,e3_;                                \
        LDSM4(h0_,h1_,h2_,h3_, sbase + SM_KH + off_);                            \
        LDSM4(e0_,e1_,e2_,e3_, sbase + SM_KL + off_);                            \
        HMMA((SN)[2*np_],   qh[kk], h0_, h1_);                                   \
        HMMA((SN)[2*np_],   ql[kk], h0_, h1_);                                   \
        HMMA((SN)[2*np_],   qh[kk], e0_, e1_);                                   \
        HMMA((SN)[2*np_+1], qh[kk], h2_, h3_);                                   \
        HMMA((SN)[2*np_+1], ql[kk], h2_, h3_);                                   \
        HMMA((SN)[2*np_+1], qh[kk], e2_, e3_);                                   \
    } }

#define EXP_PACK(i, SC) {                                                        \
    float p0_ = ex2((SC)[i][0] - mn0);                                           \
    float p1_ = ex2((SC)[i][1] - mn0);                                           \
    float p2_ = ex2((SC)[i][2] - mn1);                                           \
    float p3_ = ex2((SC)[i][3] - mn1);                                           \
    rs0 += p0_ + p1_; rs1 += p2_ + p3_;                                          \
    uint32_t h01_ = cvt2bf(p1_, p0_);                                            \
    uint32_t h23_ = cvt2bf(p3_, p2_);                                            \
    PH0[i] = h01_; PH1[i] = h23_;                                                \
    float q0_ = p0_ - __uint_as_float(h01_ << 16);                               \
    float q1_ = p1_ - __uint_as_float(h01_ & 0xFFFF0000u);                       \
    float q2_ = p2_ - __uint_as_float(h23_ << 16);                               \
    float q3_ = p3_ - __uint_as_float(h23_ & 0xFFFF0000u);                       \
    PL0[i] = cvt2bf(q1_, q0_); PL1[i] = cvt2bf(q3_, q2_); }

#define PV_STEP(kk) {                                                            \
    uint32_t aH_[4] = { PH0[2*(kk)], PH1[2*(kk)], PH0[2*(kk)+1], PH1[2*(kk)+1] };\
    uint32_t aL_[4] = { PL0[2*(kk)], PL1[2*(kk)], PL0[2*(kk)+1], PL1[2*(kk)+1] };\
    _Pragma("unroll")                                                            \
    for (int np_ = 0; np_ < 4; np_++) {                                          \
        uint32_t off_ = ob0 + (16u*(kk) + v_row)*VPITCH + 32u*np_ + v_col;       \
        uint32_t h0_,h1_,h2_,h3_,e0_,e1_,e2_,e3_;                                \
        LDSM4T(h0_,h1_,h2_,h3_, sbase + SM_VH + off_);                           \
        LDSM4T(e0_,e1_,e2_,e3_, sbase + SM_VL + off_);                           \
        HMMA(o_acc[2*np_],   aH_, h0_, h1_);                                     \
        HMMA(o_acc[2*np_],   aL_, h0_, h1_);                                     \
        HMMA(o_acc[2*np_],   aH_, e0_, e1_);                                     \
        HMMA(o_acc[2*np_+1], aH_, h2_, h3_);                                     \
        HMMA(o_acc[2*np_+1], aL_, h2_, h3_);                                     \
        HMMA(o_acc[2*np_+1], aH_, e2_, e3_);                                     \
    } }

#define LDG_TILE(T) {                                                            \
    const int k0n_ = (T) * BK;                                                   \
    _Pragma("unroll")                                                            \
    for (int it_ = 0; it_ < 8; it_++) {                                          \
        int r_ = k0n_ + kr + it_ * 8;                                            \
        const float* src_ = (kc < TD) ? (Kb + (size_t)r_ * TD + kc)              \
                                      : (Kpb + (size_t)r_ * TD + (kc - TD));     \
        kreg[it_] = *(const float4*)src_;                                        \
    }                                                                            \
    _Pragma("unroll")                                                            \
    for (int it_ = 0; it_ < 4; it_++)                                            \
        vreg[it_] = *(const float4*)(Vb + (size_t)(k0n_ + vr + it_ * 16) * TD + vc); }

#define STS_TILE(OB) {                                                           \
    _Pragma("unroll")                                                            \
    for (int it_ = 0; it_ < 8; it_++) {                                          \
        uint32_t o_ = (OB) + (uint32_t)(kr + it_ * 8) * KPITCH + (uint32_t)kc * 2; \
        split_store(smem, SM_KH + o_, SM_KL + o_, kreg[it_]);                    \
    }                                                                            \
    _Pragma("unroll")                                                            \
    for (int it_ = 0; it_ < 4; it_++) {                                          \
        uint32_t o_ = (OB) + (uint32_t)(vr + it_ * 16) * VPITCH + (uint32_t)vc * 2; \
        split_store(smem, SM_VH + o_, SM_VL + o_, vreg[it_]);                    \
    } }

// body(kt): STS(kt+2); QK(kt+1) interleaved with softmax(kt); LDG(kt+3); PV(kt)
#define BODY(KT, SC, SN) do {                                                    \
    const int kt_ = (KT);                                                        \
    if (kt_ + 2 < NTILES) STS_TILE(ob2);                                         \
    const bool doqk_ = (kt_ + 1 < NTILES);                                       \
    if (doqk_) {                                                                 \
        _Pragma("unroll") for (int i_=0;i_<8;i_++)                               \
            _Pragma("unroll") for (int j_=0;j_<4;j_++) (SN)[i_][j_] = 0.0f;      \
        QK_STEP(0, SN, ob1); QK_STEP(1, SN, ob1);                                \
    }                                                                            \
    float tm0 = -1e30f, tm1 = -1e30f;                                            \
    _Pragma("unroll") for (int i_=0;i_<4;i_++) {                                 \
        tm0 = fmaxf(tm0, fmaxf((SC)[i_][0], (SC)[i_][1]));                       \
        tm1 = fmaxf(tm1, fmaxf((SC)[i_][2], (SC)[i_][3])); }                     \
    if (doqk_) { QK_STEP(2, SN, ob1); QK_STEP(3, SN, ob1); }                     \
    _Pragma("unroll") for (int i_=4;i_<8;i_++) {                                 \
        tm0 = fmaxf(tm0, fmaxf((SC)[i_][0], (SC)[i_][1]));                       \
        tm1 = fmaxf(tm1, fmaxf((SC)[i_][2], (SC)[i_][3])); }                     \
    tm0 = fmaxf(tm0, __shfl_xor_sync(0xffffffffu, tm0, 1));                      \
    tm0 = fmaxf(tm0, __shfl_xor_sync(0xffffffffu, tm0, 2));                      \
    tm1 = fmaxf(tm1, __shfl_xor_sync(0xffffffffu, tm1, 1));                      \
    tm1 = fmaxf(tm1, __shfl_xor_sync(0xffffffffu, tm1, 2));                      \
    float mn0 = fmaxf(m0, tm0), mn1 = fmaxf(m1, tm1);                            \
    float a0 = ex2(m0 - mn0), a1 = ex2(m1 - mn1);                                \
    m0 = mn0; m1 = mn1;                                                          \
    if (doqk_) { QK_STEP(4, SN, ob1); QK_STEP(5, SN, ob1); }                     \
    float rs0 = 0.0f, rs1 = 0.0f;                                                \
    uint32_t PH0[8], PH1[8], PL0[8], PL1[8];                                     \
    _Pragma("unroll") for (int i_=0;i_<4;i_++) EXP_PACK(i_, SC);                 \
    if (doqk_) { QK_STEP(6, SN, ob1); QK_STEP(7, SN, ob1); }                     \
    _Pragma("unroll") for (int i_=4;i_<8;i_++) EXP_PACK(i_, SC);                 \
    rs0 += __shfl_xor_sync(0xffffffffu, rs0, 1);                                 \
    rs0 += __shfl_xor_sync(0xffffffffu, rs0, 2);                                 \
    rs1 += __shfl_xor_sync(0xffffffffu, rs1, 1);                                 \
    rs1 += __shfl_xor_sync(0xffffffffu, rs1, 2);                                 \
    l0 = l0 * a0 + rs0; l1 = l1 * a1 + rs1;                                      \
    _Pragma("unroll") for (int i_=0;i_<8;i_++) {                                 \
        o_acc[i_][0] *= a0; o_acc[i_][1] *= a0;                                  \
        o_acc[i_][2] *= a1; o_acc[i_][3] *= a1; }                                \
    if (kt_ + 3 < NTILES) LDG_TILE(kt_ + 3);                                     \
    PV_STEP(0); PV_STEP(1); PV_STEP(2); PV_STEP(3);                              \
    { uint32_t t_ = ob0; ob0 = ob1; ob1 = ob2; ob2 = t_; }                       \
    __syncthreads();                                                             \
} while (0)

__global__ __launch_bounds__(NT, 1)
void sdpa_fa_pipe_kernel(const float* __restrict__ Qg,
                         const float* __restrict__ Kg,
                         const float* __restrict__ Vg,
                         const float* __restrict__ Qpg,
                         const float* __restrict__ Kpg,
                         float* __restrict__ Og)
{
    extern __shared__ char smem[];
    const uint32_t sbase = smem_u32(smem);

    const int tid  = threadIdx.x;
    const int wid  = tid >> 5;
    const int lane = tid & 31;

    const int bh = blockIdx.y;
    const int q0 = blockIdx.x * BQ;
    const size_t bh_off = (size_t)bh * TSEQ * TD;
    const float* Qb  = Qg  + bh_off;
    const float* Qpb = Qpg + bh_off;
    const float* Kb  = Kg  + bh_off;
    const float* Kpb = Kpg + bh_off;
    const float* Vb  = Vg  + bh_off;

    const int kr = tid >> 5;
    const int kc = (tid & 31) << 2;
    const int vr = tid >> 4;
    const int vc = (tid & 15) << 2;

    // ---- stage Q' scaled by (1/8)*log2(e) (base-2 softmax) ----
    const float scale = 0.125f * 1.4426950408889634f;
    #pragma unroll
    for (int it = 0; it < 16; it++) {
        int idx4 = tid + it * NT;
        int r = idx4 >> 5;
        int c = (idx4 & 31) << 2;
        const float* src = (c < TD) ? (Qb + (size_t)(q0 + r) * TD + c)
                                    : (Qpb + (size_t)(q0 + r) * TD + (c - TD));
        float4 v = *(const float4*)src;
        v.x *= scale; v.y *= scale; v.z *= scale; v.w *= scale;
        uint32_t o = (uint32_t)r * KPITCH + (uint32_t)c * 2;
        split_store(smem, SM_QH + o, SM_QL + o, v);
    }
    __syncthreads();

    uint32_t qh[8][4], ql[8][4];
    {
        uint32_t row = (uint32_t)(16 * wid) + (lane & 7) + ((lane >> 3) & 1) * 8;
        uint32_t base_r = row * KPITCH;
        uint32_t cshift = ((uint32_t)(lane >> 4)) * 16;
        #pragma unroll
        for (int kk = 0; kk < 8; kk++) {
            uint32_t off = base_r + (uint32_t)kk * 32 + cshift;
            LDSM4(qh[kk][0], qh[kk][1], qh[kk][2], qh[kk][3], sbase + SM_QH + off);
            LDSM4(ql[kk][0], ql[kk][1], ql[kk][2], ql[kk][3], sbase + SM_QL + off);
        }
    }
    __syncthreads();   // Q staging free for buffers

    const uint32_t k_row  = (lane & 7) + ((lane >> 4) & 1) * 8;
    const uint32_t k_kseg = ((lane >> 3) & 1) * 16;
    const uint32_t v_row  = (lane & 7) + ((lane >> 3) & 1) * 8;
    const uint32_t v_col  = ((uint32_t)(lane >> 4)) * 16;

    float4 kreg[8], vreg[4];
    // tiles 0,1 into buffers 0,1; tile 2 stays in regs for body(0)'s STS
    LDG_TILE(0); STS_TILE(0u);
    LDG_TILE(1); STS_TILE((uint32_t)BUFSZ);
    LDG_TILE(2);
    __syncthreads();

    float o_acc[8][4];
    #pragma unroll
    for (int i = 0; i < 8; i++)
        #pragma unroll
        for (int j = 0; j < 4; j++) o_acc[i][j] = 0.0f;
    float m0 = -1e30f, m1 = -1e30f, l0 = 0.0f, l1 = 0.0f;

    float sA[8][4], sB[8][4];
    // precompute QK(0) -> sA
    #pragma unroll
    for (int i = 0; i < 8; i++)
        #pragma unroll
        for (int j = 0; j < 4; j++) sA[i][j] = 0.0f;
    QK_STEP(0, sA, 0u); QK_STEP(1, sA, 0u); QK_STEP(2, sA, 0u); QK_STEP(3, sA, 0u);
    QK_STEP(4, sA, 0u); QK_STEP(5, sA, 0u); QK_STEP(6, sA, 0u); QK_STEP(7, sA, 0u);

    uint32_t ob0 = 0, ob1 = BUFSZ, ob2 = 2 * BUFSZ;

    for (int kt2 = 0; kt2 < NTILES; kt2 += 2) {
        BODY(kt2,     sA, sB);
        BODY(kt2 + 1, sB, sA);
    }

    // ================= epilogue =================
    float inv0 = 1.0f / l0, inv1 = 1.0f / l1;
    int row0 = 16 * wid + (lane >> 2);
    int row1 = row0 + 8;
    int colb = 2 * (lane & 3);
    size_t obase = ((size_t)bh * TSEQ + q0);
    #pragma unroll
    for (int i = 0; i < 8; i++) {
        int col = 8 * i + colb;
        *(float2*)(Og + (obase + row0) * TD + col) =
            make_float2(o_acc[i][0] * inv0, o_acc[i][1] * inv0);
        *(float2*)(Og + (obase + row1) * TD + col) =
            make_float2(o_acc[i][2] * inv1, o_acc[i][3] * inv1);
    }
}

extern "C" void kernel_launch(void* const* d_in, const int* in_sizes, int n_in,
                              void* d_out, int out_size)
{
    const float* Q  = (const float*)d_in[0];
    const float* K  = (const float*)d_in[1];
    const float* V  = (const float*)d_in[2];
    const float* Qp = (const float*)d_in[3];
    const float* Kp = (const float*)d_in[4];
    float* O = (float*)d_out;

    cudaFuncSetAttribute(sdpa_fa_pipe_kernel,
                         cudaFuncAttributeMaxDynamicSharedMemorySize, SMEM_TOTAL);

    dim3 grid(TSEQ / BQ, 2 * 16);   // (16, 32)
    sdpa_fa_pipe_kernel<<<grid, NT, SMEM_TOTAL>>>(Q, K, V, Qp, Kp, O);
}

// round 15
// speedup vs baseline: 1.6609x; 1.6609x over previous
#include <cuda_runtime.h>
#include <cuda_bf16.h>
#include <cstdint>

// ---------------- problem constants ----------------
#define TSEQ 2048
#define TD   64
#define BQ   128            // q rows per CTA (32 per warp)
#define BK   64             // kv rows per tile
#define NT   128            // 4 warps
#define NTILES (TSEQ/BK)    // 32

// ---------------- SMEM (bytes, dynamic) ----------------
// QL persistent @0: 128 rows x 272 B = 34,816
// K/V buffer @34,816: KH(17408) KL(17408) VH(9216) VL(9216) = 53,248
#define KPITCH 272
#define VPITCH 144
#define QL_BASE 0
#define BUF 34816
#define SM_KH (BUF + 0)
#define SM_KL (BUF + 17408)
#define SM_VH (BUF + 34816)
#define SM_VL (BUF + 44032)
#define SMEM_TOTAL (BUF + 53248)    // 88,064 B -> 2 CTAs/SM = 176,128 B
#define SM_QH BUF                   // prologue-only Qh staging inside buffer

__device__ __forceinline__ uint32_t smem_u32(const void* p) {
    uint32_t a;
    asm("{ .reg .u64 t; cvta.to.shared.u64 t, %1; cvt.u32.u64 %0, t; }" : "=r"(a) : "l"(p));
    return a;
}
__device__ __forceinline__ uint32_t cvt2bf(float e1, float e0) {
    uint32_t r;
    asm("cvt.rn.bf16x2.f32 %0, %1, %2;" : "=r"(r) : "f"(e1), "f"(e0));
    return r;
}
__device__ __forceinline__ float ex2(float x) {
    float y;
    asm("ex2.approx.f32 %0, %1;" : "=f"(y) : "f"(x));
    return y;
}

#define HMMA(d, a, b0, b1)                                                       \
    asm volatile("mma.sync.aligned.m16n8k16.row.col.f32.bf16.bf16.f32 "          \
        "{%0,%1,%2,%3}, {%4,%5,%6,%7}, {%8,%9}, {%0,%1,%2,%3};"                  \
        : "+f"((d)[0]), "+f"((d)[1]), "+f"((d)[2]), "+f"((d)[3])                 \
        : "r"((a)[0]), "r"((a)[1]), "r"((a)[2]), "r"((a)[3]), "r"(b0), "r"(b1))

#define LDSM4(r0, r1, r2, r3, addr)                                              \
    asm volatile("ldmatrix.sync.aligned.m8n8.x4.shared.b16 {%0,%1,%2,%3}, [%4];" \
        : "=r"(r0), "=r"(r1), "=r"(r2), "=r"(r3) : "r"(addr))

#define LDSM4T(r0, r1, r2, r3, addr)                                             \
    asm volatile("ldmatrix.sync.aligned.m8n8.x4.trans.shared.b16 {%0,%1,%2,%3}, [%4];" \
        : "=r"(r0), "=r"(r1), "=r"(r2), "=r"(r3) : "r"(addr))

__device__ __forceinline__ void split_store(char* sm, uint32_t off_h, uint32_t off_l,
                                            float4 v) {
    uint32_t h01 = cvt2bf(v.y, v.x);
    uint32_t h23 = cvt2bf(v.w, v.z);
    float r0 = v.x - __uint_as_float(h01 << 16);
    float r1 = v.y - __uint_as_float(h01 & 0xFFFF0000u);
    float r2 = v.z - __uint_as_float(h23 << 16);
    float r3 = v.w - __uint_as_float(h23 & 0xFFFF0000u);
    *(uint2*)(sm + off_h) = make_uint2(h01, h23);
    *(uint2*)(sm + off_l) = make_uint2(cvt2bf(r1, r0), cvt2bf(r3, r2));
}

__global__ __launch_bounds__(NT, 2)
void sdpa_w32_kernel(const float* __restrict__ Qg,
                     const float* __restrict__ Kg,
                     const float* __restrict__ Vg,
                     const float* __restrict__ Qpg,
                     const float* __restrict__ Kpg,
                     float* __restrict__ Og)
{
    extern __shared__ char smem[];
    const uint32_t sbase = smem_u32(smem);

    const int tid  = threadIdx.x;
    const int wid  = tid >> 5;
    const int lane = tid & 31;

    const int bh = blockIdx.y;
    const int q0 = blockIdx.x * BQ;
    const size_t bh_off = (size_t)bh * TSEQ * TD;
    const float* Kb  = Kg  + bh_off;
    const float* Kpb = Kpg + bh_off;
    const float* Vb  = Vg  + bh_off;

    // ===== prologue: stage Q' scaled by (1/8)*log2(e); hi->buffer, lo->QL =====
    {
        const float* Qb  = Qg  + bh_off;
        const float* Qpb = Qpg + bh_off;
        const float scale = 0.125f * 1.4426950408889634f;
        #pragma unroll
        for (int it = 0; it < 32; it++) {
            int idx4 = tid + it * NT;
            int r = idx4 >> 5;                  // 128 rows, 32 float4/row
            int c = (idx4 & 31) << 2;
            const float* src = (c < TD) ? (Qb + (size_t)(q0 + r) * TD + c)
                                        : (Qpb + (size_t)(q0 + r) * TD + (c - TD));
            float4 v = *(const float4*)src;
            v.x *= scale; v.y *= scale; v.z *= scale; v.w *= scale;
            uint32_t o = (uint32_t)r * KPITCH + (uint32_t)c * 2;
            split_store(smem, SM_QH + o, QL_BASE + o, v);
        }
    }
    __syncthreads();

    // A-frag row addressing (per 16-row block rb)
    const uint32_t a_sub = (lane & 7) + ((lane >> 3) & 1) * 8;
    const uint32_t a_seg = ((uint32_t)(lane >> 4)) * 16;
    uint32_t a_base[2];
    #pragma unroll
    for (int rb = 0; rb < 2; rb++)
        a_base[rb] = ((uint32_t)(32 * wid + 16 * rb) + a_sub) * KPITCH + a_seg;

    // ----- Qh fragments to registers (2 rb x 8 kk x 4) -----
    uint32_t qh[2][8][4];
    #pragma unroll
    for (int rb = 0; rb < 2; rb++)
        #pragma unroll
        for (int kk = 0; kk < 8; kk++)
            LDSM4(qh[rb][kk][0], qh[rb][kk][1], qh[rb][kk][2], qh[rb][kk][3],
                  sbase + SM_QH + a_base[rb] + (uint32_t)kk * 32);
    __syncthreads();   // buffer free for K/V

    // ===== state =====
    float o_acc[2][8][4];
    #pragma unroll
    for (int rb = 0; rb < 2; rb++)
        #pragma unroll
        for (int i = 0; i < 8; i++)
            #pragma unroll
            for (int j = 0; j < 4; j++) o_acc[rb][i][j] = 0.0f;
    float m[4], l[4];
    #pragma unroll
    for (int i = 0; i < 4; i++) { m[i] = -1e30f; l[i] = 0.0f; }

    const uint32_t k_row  = (lane & 7) + ((lane >> 4) & 1) * 8;
    const uint32_t k_kseg = ((lane >> 3) & 1) * 16;
    const uint32_t v_row  = (lane & 7) + ((lane >> 3) & 1) * 8;
    const uint32_t v_col  = ((uint32_t)(lane >> 4)) * 16;

    for (int kt = 0; kt < NTILES; kt++) {
        const int k0 = kt * BK;

        // ---- load K'/V tile into the single buffer (co-CTA hides latency) ----
        #pragma unroll
        for (int it = 0; it < 16; it++) {
            int idx4 = tid + it * NT;
            int r = idx4 >> 5;
            int c = (idx4 & 31) << 2;
            const float* src = (c < TD) ? (Kb + (size_t)(k0 + r) * TD + c)
                                        : (Kpb + (size_t)(k0 + r) * TD + (c - TD));
            float4 v = *(const float4*)src;
            uint32_t o = (uint32_t)r * KPITCH + (uint32_t)c * 2;
            split_store(smem, SM_KH + o, SM_KL + o, v);
        }
        #pragma unroll
        for (int it = 0; it < 8; it++) {
            int idx4 = tid + it * NT;
            int r = idx4 >> 4;
            int c = (idx4 & 15) << 2;
            float4 v = *(const float4*)(Vb + (size_t)(k0 + r) * TD + c);
            uint32_t o = (uint32_t)r * VPITCH + (uint32_t)c * 2;
            split_store(smem, SM_VH + o, SM_VL + o, v);
        }
        __syncthreads();

        // ---- S = Qh*Kh + Qh*Kl + Ql*Kh   (32 rows x 64 keys per warp) ----
        float s[2][8][4];
        #pragma unroll
        for (int rb = 0; rb < 2; rb++)
            #pragma unroll
            for (int i = 0; i < 8; i++)
                #pragma unroll
                for (int j = 0; j < 4; j++) s[rb][i][j] = 0.0f;

        #pragma unroll
        for (int kk = 0; kk < 8; kk++) {
            uint32_t ql0[4], ql1[4];
            LDSM4(ql0[0], ql0[1], ql0[2], ql0[3],
                  sbase + QL_BASE + a_base[0] + (uint32_t)kk * 32);
            LDSM4(ql1[0], ql1[1], ql1[2], ql1[3],
                  sbase + QL_BASE + a_base[1] + (uint32_t)kk * 32);
            #pragma unroll
            for (int np = 0; np < 4; np++) {
                uint32_t off = (16u * np + k_row) * KPITCH + (uint32_t)kk * 32 + k_kseg;
                uint32_t h0, h1, h2, h3, e0, e1, e2, e3;
                LDSM4(h0, h1, h2, h3, sbase + SM_KH + off);
                LDSM4(e0, e1, e2, e3, sbase + SM_KL + off);
                HMMA(s[0][2 * np],     qh[0][kk], h0, h1);
                HMMA(s[0][2 * np],     ql0,       h0, h1);
                HMMA(s[0][2 * np],     qh[0][kk], e0, e1);
                HMMA(s[0][2 * np + 1], qh[0][kk], h2, h3);
                HMMA(s[0][2 * np + 1], ql0,       h2, h3);
                HMMA(s[0][2 * np + 1], qh[0][kk], e2, e3);
                HMMA(s[1][2 * np],     qh[1][kk], h0, h1);
                HMMA(s[1][2 * np],     ql1,       h0, h1);
                HMMA(s[1][2 * np],     qh[1][kk], e0, e1);
                HMMA(s[1][2 * np + 1], qh[1][kk], h2, h3);
                HMMA(s[1][2 * np + 1], ql1,       h2, h3);
                HMMA(s[1][2 * np + 1], qh[1][kk], e2, e3);
            }
        }

        // ---- online softmax: 4 row-groups per thread ----
        float tm[4];
        #pragma unroll
        for (int i = 0; i < 4; i++) tm[i] = -1e30f;
        #pragma unroll
        for (int rb = 0; rb < 2; rb++)
            #pragma unroll
            for (int i = 0; i < 8; i++) {
                tm[2 * rb]     = fmaxf(tm[2 * rb],     fmaxf(s[rb][i][0], s[rb][i][1]));
                tm[2 * rb + 1] = fmaxf(tm[2 * rb + 1], fmaxf(s[rb][i][2], s[rb][i][3]));
            }
        float a[4], rs[4];
        #pragma unroll
        for (int g = 0; g < 4; g++) {
            tm[g] = fmaxf(tm[g], __shfl_xor_sync(0xffffffffu, tm[g], 1));
            tm[g] = fmaxf(tm[g], __shfl_xor_sync(0xffffffffu, tm[g], 2));
            float mn = fmaxf(m[g], tm[g]);
            a[g] = ex2(m[g] - mn);
            m[g] = mn;
            rs[g] = 0.0f;
        }

        uint32_t ph0[2][8], ph1[2][8], pl0[2][8], pl1[2][8];
        #pragma unroll
        for (int rb = 0; rb < 2; rb++)
            #pragma unroll
            for (int i = 0; i < 8; i++) {
                float p0 = ex2(s[rb][i][0] - m[2 * rb]);
                float p1 = ex2(s[rb][i][1] - m[2 * rb]);
                float p2 = ex2(s[rb][i][2] - m[2 * rb + 1]);
                float p3 = ex2(s[rb][i][3] - m[2 * rb + 1]);
                rs[2 * rb]     += p0 + p1;
                rs[2 * rb + 1] += p2 + p3;
                uint32_t h01 = cvt2bf(p1, p0);
                uint32_t h23 = cvt2bf(p3, p2);
                ph0[rb][i] = h01; ph1[rb][i] = h23;
                float r0 = p0 - __uint_as_float(h01 << 16);
                float r1 = p1 - __uint_as_float(h01 & 0xFFFF0000u);
                float r2 = p2 - __uint_as_float(h23 << 16);
                float r3 = p3 - __uint_as_float(h23 & 0xFFFF0000u);
                pl0[rb][i] = cvt2bf(r1, r0);
                pl1[rb][i] = cvt2bf(r3, r2);
            }
        #pragma unroll
        for (int g = 0; g < 4; g++) {
            rs[g] += __shfl_xor_sync(0xffffffffu, rs[g], 1);
            rs[g] += __shfl_xor_sync(0xffffffffu, rs[g], 2);
            l[g] = l[g] * a[g] + rs[g];
        }
        #pragma unroll
        for (int rb = 0; rb < 2; rb++)
            #pragma unroll
            for (int i = 0; i < 8; i++) {
                o_acc[rb][i][0] *= a[2 * rb];     o_acc[rb][i][1] *= a[2 * rb];
                o_acc[rb][i][2] *= a[2 * rb + 1]; o_acc[rb][i][3] *= a[2 * rb + 1];
            }

        // ---- O += Ph*Vh + Ph*Vl + Pl*Vh  (V frags shared across both rbs) ----
        #pragma unroll
        for (int kk2 = 0; kk2 < 4; kk2++) {
            uint32_t aH0[4] = { ph0[0][2*kk2], ph1[0][2*kk2], ph0[0][2*kk2+1], ph1[0][2*kk2+1] };
            uint32_t aL0[4] = { pl0[0][2*kk2], pl1[0][2*kk2], pl0[0][2*kk2+1], pl1[0][2*kk2+1] };
            uint32_t aH1[4] = { ph0[1][2*kk2], ph1[1][2*kk2], ph0[1][2*kk2+1], ph1[1][2*kk2+1] };
            uint32_t aL1[4] = { pl0[1][2*kk2], pl1[1][2*kk2], pl0[1][2*kk2+1], pl1[1][2*kk2+1] };
            #pragma unroll
            for (int np = 0; np < 4; np++) {
                uint32_t off = (16u * kk2 + v_row) * VPITCH + 32u * np + v_col;
                uint32_t h0, h1, h2, h3, e0, e1, e2, e3;
                LDSM4T(h0, h1, h2, h3, sbase + SM_VH + off);
                LDSM4T(e0, e1, e2, e3, sbase + SM_VL + off);
                HMMA(o_acc[0][2 * np],     aH0, h0, h1);
                HMMA(o_acc[0][2 * np],     aL0, h0, h1);
                HMMA(o_acc[0][2 * np],     aH0, e0, e1);
                HMMA(o_acc[0][2 * np + 1], aH0, h2, h3);
                HMMA(o_acc[0][2 * np + 1], aL0, h2, h3);
                HMMA(o_acc[0][2 * np + 1], aH0, e2, e3);
                HMMA(o_acc[1][2 * np],     aH1, h0, h1);
                HMMA(o_acc[1][2 * np],     aL1, h0, h1);
                HMMA(o_acc[1][2 * np],     aH1, e0, e1);
                HMMA(o_acc[1][2 * np + 1], aH1, h2, h3);
                HMMA(o_acc[1][2 * np + 1], aL1, h2, h3);
                HMMA(o_acc[1][2 * np + 1], aH1, e2, e3);
            }
        }
        __syncthreads();   // buffer consumed; next iteration may overwrite
    }

    // ================= epilogue =================
    const int colb = 2 * (lane & 3);
    const size_t obase = ((size_t)bh * TSEQ + q0);
    #pragma unroll
    for (int rb = 0; rb < 2; rb++) {
        float inv0 = 1.0f / l[2 * rb];
        float inv1 = 1.0f / l[2 * rb + 1];
        int row0 = 32 * wid + 16 * rb + (lane >> 2);
        int row1 = row0 + 8;
        #pragma unroll
        for (int i = 0; i < 8; i++) {
            int col = 8 * i + colb;
            *(float2*)(Og + (obase + row0) * TD + col) =
                make_float2(o_acc[rb][i][0] * inv0, o_acc[rb][i][1] * inv0);
            *(float2*)(Og + (obase + row1) * TD + col) =
                make_float2(o_acc[rb][i][2] * inv1, o_acc[rb][i][3] * inv1);
        }
    }
}

extern "C" void kernel_launch(void* const* d_in, const int* in_sizes, int n_in,
                              void* d_out, int out_size)
{
    const float* Q  = (const float*)d_in[0];
    const float* K  = (const float*)d_in[1];
    const float* V  = (const float*)d_in[2];
    const float* Qp = (const float*)d_in[3];
    const float* Kp = (const float*)d_in[4];
    float* O = (float*)d_out;

    cudaFuncSetAttribute(sdpa_w32_kernel,
                         cudaFuncAttributeMaxDynamicSharedMemorySize, SMEM_TOTAL);

    dim3 grid(TSEQ / BQ, 2 * 16);   // (16, 32) = 512 CTAs, 2 per SM
    sdpa_w32_kernel<<<grid, NT, SMEM_TOTAL>>>(Q, K, V, Qp, Kp, O);
}

// round 16
// speedup vs baseline: 1.6765x; 1.0094x over previous
#include <cuda_runtime.h>
#include <cuda_bf16.h>
#include <cstdint>

// ---------------- problem constants ----------------
#define TSEQ 2048
#define TD   64
#define TDK  128            // combined head dim [Q|Qpos]
#define BQ   128            // q rows per CTA
#define BK   64             // kv rows per tile
#define NT   256            // 8 warps
#define NTILES (TSEQ/BK)    // 32

// ---------------- SMEM (bytes, dynamic), double buffered ----------------
// per buffer: KH [64][136]bf16 @0, KL @17408, VH [64][72]bf16 @34816, VL @44032
#define KPITCH 272
#define VPITCH 144
#define SM_KH 0
#define SM_KL 17408
#define SM_VH 34816
#define SM_VL 44032
#define BUFSZ 53248
#define SMEM_TOTAL (2*BUFSZ)          // 106,496 B
// Q staging (prologue only, spans buffer region): hi @0, lo @34816
#define SM_QH 0
#define SM_QL 34816

__device__ __forceinline__ uint32_t smem_u32(const void* p) {
    uint32_t a;
    asm("{ .reg .u64 t; cvta.to.shared.u64 t, %1; cvt.u32.u64 %0, t; }" : "=r"(a) : "l"(p));
    return a;
}
// pack two fp32 -> bf16x2 (e0 -> low half, e1 -> high half)
__device__ __forceinline__ uint32_t cvt2bf(float e1, float e0) {
    uint32_t r;
    asm("cvt.rn.bf16x2.f32 %0, %1, %2;" : "=r"(r) : "f"(e1), "f"(e0));
    return r;
}
__device__ __forceinline__ float ex2(float x) {
    float y;
    asm("ex2.approx.f32 %0, %1;" : "=f"(y) : "f"(x));
    return y;
}

// NOTE: NOT volatile — pure register dataflow; lets ptxas software-pipeline
// and interleave independent accumulator chains to hide HMMA latency.
#define HMMA(d, a, b0, b1)                                                       \
    asm("mma.sync.aligned.m16n8k16.row.col.f32.bf16.bf16.f32 "                   \
        "{%0,%1,%2,%3}, {%4,%5,%6,%7}, {%8,%9}, {%0,%1,%2,%3};"                  \
        : "+f"((d)[0]), "+f"((d)[1]), "+f"((d)[2]), "+f"((d)[3])                 \
        : "r"((a)[0]), "r"((a)[1]), "r"((a)[2]), "r"((a)[3]), "r"(b0), "r"(b1))

#define LDSM4(r0, r1, r2, r3, addr)                                              \
    asm volatile("ldmatrix.sync.aligned.m8n8.x4.shared.b16 {%0,%1,%2,%3}, [%4];" \
        : "=r"(r0), "=r"(r1), "=r"(r2), "=r"(r3) : "r"(addr))

#define LDSM4T(r0, r1, r2, r3, addr)                                             \
    asm volatile("ldmatrix.sync.aligned.m8n8.x4.trans.shared.b16 {%0,%1,%2,%3}, [%4];" \
        : "=r"(r0), "=r"(r1), "=r"(r2), "=r"(r3) : "r"(addr))

// split one float4 into hi/lo bf16x2 pairs, 8B stores at byte offsets
__device__ __forceinline__ void split_store(char* sm, uint32_t off_h, uint32_t off_l,
                                            float4 v) {
    uint32_t h01 = cvt2bf(v.y, v.x);
    uint32_t h23 = cvt2bf(v.w, v.z);
    float r0 = v.x - __uint_as_float(h01 << 16);
    float r1 = v.y - __uint_as_float(h01 & 0xFFFF0000u);
    float r2 = v.z - __uint_as_float(h23 << 16);
    float r3 = v.w - __uint_as_float(h23 & 0xFFFF0000u);
    *(uint2*)(sm + off_h) = make_uint2(h01, h23);
    *(uint2*)(sm + off_l) = make_uint2(cvt2bf(r1, r0), cvt2bf(r3, r2));
}

__global__ __launch_bounds__(NT, 1)
void sdpa_mma_ilp_kernel(const float* __restrict__ Qg,
                         const float* __restrict__ Kg,
                         const float* __restrict__ Vg,
                         const float* __restrict__ Qpg,
                         const float* __restrict__ Kpg,
                         float* __restrict__ Og)
{
    extern __shared__ char smem[];
    const uint32_t sbase = smem_u32(smem);

    const int tid  = threadIdx.x;
    const int wid  = tid >> 5;
    const int lane = tid & 31;

    const int bh = blockIdx.y;
    const int q0 = blockIdx.x * BQ;
    const size_t bh_off = (size_t)bh * TSEQ * TD;
    const float* Qb  = Qg  + bh_off;
    const float* Qpb = Qpg + bh_off;
    const float* Kb  = Kg  + bh_off;
    const float* Kpb = Kpg + bh_off;
    const float* Vb  = Vg  + bh_off;

    // per-thread load coordinates (fixed across tiles)
    const int kr = tid >> 5;                 // K row group: 8 rows strided by 8
    const int kc = (tid & 31) << 2;          // K col (d) group
    const int vr = tid >> 4;                 // V row group: 16 rows strided by 16
    const int vc = (tid & 15) << 2;          // V col group

    // ================= stage Q' (scaled by (1/8)*log2e), split hi/lo =========
    const float scale = 0.125f * 1.4426950408889634f;
    #pragma unroll
    for (int it = 0; it < 16; it++) {
        int idx4 = tid + it * NT;
        int r = idx4 >> 5;
        int c = (idx4 & 31) << 2;
        const float* src = (c < TD) ? (Qb + (size_t)(q0 + r) * TD + c)
                                    : (Qpb + (size_t)(q0 + r) * TD + (c - TD));
        float4 v = *(const float4*)src;
        v.x *= scale; v.y *= scale; v.z *= scale; v.w *= scale;
        uint32_t o = (uint32_t)r * KPITCH + (uint32_t)c * 2;
        split_store(smem, SM_QH + o, SM_QL + o, v);
    }
    __syncthreads();

    // ----- issue tile-0 prefetch LDGs (don't touch smem) -----
    float4 kreg[8], vreg[4];
    #pragma unroll
    for (int it = 0; it < 8; it++) {
        int r = kr + it * 8;
        const float* src = (kc < TD) ? (Kb + (size_t)r * TD + kc)
                                     : (Kpb + (size_t)r * TD + (kc - TD));
        kreg[it] = *(const float4*)src;
    }
    #pragma unroll
    for (int it = 0; it < 4; it++)
        vreg[it] = *(const float4*)(Vb + (size_t)(vr + it * 16) * TD + vc);

    // ----- extract Q a-fragments (warp rows 16w .. 16w+15) -----
    uint32_t qh[8][4], ql[8][4];
    {
        uint32_t row = (uint32_t)(16 * wid) + (lane & 7) + ((lane >> 3) & 1) * 8;
        uint32_t base_r = row * KPITCH;
        uint32_t cshift = ((uint32_t)(lane >> 4)) * 16;
        #pragma unroll
        for (int kk = 0; kk < 8; kk++) {
            uint32_t off = base_r + (uint32_t)kk * 32 + cshift;
            LDSM4(qh[kk][0], qh[kk][1], qh[kk][2], qh[kk][3], sbase + SM_QH + off);
            LDSM4(ql[kk][0], ql[kk][1], ql[kk][2], ql[kk][3], sbase + SM_QL + off);
        }
    }
    __syncthreads();   // Q staging region free

    // ----- STS tile 0 into buffer 0 -----
    #pragma unroll
    for (int it = 0; it < 8; it++) {
        uint32_t o = (uint32_t)(kr + it * 8) * KPITCH + (uint32_t)kc * 2;
        split_store(smem, SM_KH + o, SM_KL + o, kreg[it]);
    }
    #pragma unroll
    for (int it = 0; it < 4; it++) {
        uint32_t o = (uint32_t)(vr + it * 16) * VPITCH + (uint32_t)vc * 2;
        split_store(smem, SM_VH + o, SM_VL + o, vreg[it]);
    }
    __syncthreads();

    // ================= flash attention state =================
    float o_acc[8][4];
    #pragma unroll
    for (int i = 0; i < 8; i++)
        #pragma unroll
        for (int j = 0; j < 4; j++) o_acc[i][j] = 0.0f;
    float m0 = -1e30f, m1 = -1e30f, l0 = 0.0f, l1 = 0.0f;

    const uint32_t k_row  = (lane & 7) + ((lane >> 4) & 1) * 8;
    const uint32_t k_kseg = ((lane >> 3) & 1) * 16;
    const uint32_t v_row  = (lane & 7) + ((lane >> 3) & 1) * 8;
    const uint32_t v_col  = ((uint32_t)(lane >> 4)) * 16;

    for (int kt = 0; kt < NTILES; kt++) {
        const uint32_t bb = (kt & 1) ? (uint32_t)BUFSZ : 0u;   // compute buffer
        const uint32_t nb = BUFSZ - bb;                         // fill buffer

        // ---- prefetch LDGs for tile kt+1 (overlap with compute below) ----
        if (kt + 1 < NTILES) {
            const int k0n = (kt + 1) * BK;
            #pragma unroll
            for (int it = 0; it < 8; it++) {
                int r = k0n + kr + it * 8;
                const float* src = (kc < TD) ? (Kb + (size_t)r * TD + kc)
                                             : (Kpb + (size_t)r * TD + (kc - TD));
                kreg[it] = *(const float4*)src;
            }
            #pragma unroll
            for (int it = 0; it < 4; it++)
                vreg[it] = *(const float4*)(Vb + (size_t)(k0n + vr + it * 16) * TD + vc);
        }

        // ---- S = Qh*Kh + Qh*Kl + Ql*Kh  (16x64 per warp) ----
        // accumulator-interleaved order (A,B,A,B,A,B) -> dep distance 2
        float s[8][4];
        #pragma unroll
        for (int i = 0; i < 8; i++)
            #pragma unroll
            for (int j = 0; j < 4; j++) s[i][j] = 0.0f;

        #pragma unroll
        for (int kk = 0; kk < 8; kk++) {
            #pragma unroll
            for (int np = 0; np < 4; np++) {
                uint32_t off = bb + (16u * np + k_row) * KPITCH + (uint32_t)kk * 32 + k_kseg;
                uint32_t h0, h1, h2, h3, e0, e1, e2, e3;
                LDSM4(h0, h1, h2, h3, sbase + SM_KH + off);
                LDSM4(e0, e1, e2, e3, sbase + SM_KL + off);
                HMMA(s[2 * np],     qh[kk], h0, h1);
                HMMA(s[2 * np + 1], qh[kk], h2, h3);
                HMMA(s[2 * np],     ql[kk], h0, h1);
                HMMA(s[2 * np + 1], ql[kk], h2, h3);
                HMMA(s[2 * np],     qh[kk], e0, e1);
                HMMA(s[2 * np + 1], qh[kk], e2, e3);
            }
        }

        // ---- online softmax (rows: lane/4 and lane/4+8), base-2 ----
        float tm0 = -1e30f, tm1 = -1e30f;
        #pragma unroll
        for (int i = 0; i < 8; i++) {
            tm0 = fmaxf(tm0, fmaxf(s[i][0], s[i][1]));
            tm1 = fmaxf(tm1, fmaxf(s[i][2], s[i][3]));
        }
        tm0 = fmaxf(tm0, __shfl_xor_sync(0xffffffffu, tm0, 1));
        tm0 = fmaxf(tm0, __shfl_xor_sync(0xffffffffu, tm0, 2));
        tm1 = fmaxf(tm1, __shfl_xor_sync(0xffffffffu, tm1, 1));
        tm1 = fmaxf(tm1, __shfl_xor_sync(0xffffffffu, tm1, 2));
        float mn0 = fmaxf(m0, tm0), mn1 = fmaxf(m1, tm1);
        float a0 = ex2(m0 - mn0), a1 = ex2(m1 - mn1);
        m0 = mn0; m1 = mn1;

        float rs0 = 0.0f, rs1 = 0.0f;
        uint32_t ph0[8], ph1[8], pl0[8], pl1[8];
        #pragma unroll
        for (int i = 0; i < 8; i++) {
            float p0 = ex2(s[i][0] - mn0);
            float p1 = ex2(s[i][1] - mn0);
            float p2 = ex2(s[i][2] - mn1);
            float p3 = ex2(s[i][3] - mn1);
            rs0 += p0 + p1; rs1 += p2 + p3;
            uint32_t h01 = cvt2bf(p1, p0);
            uint32_t h23 = cvt2bf(p3, p2);
            ph0[i] = h01; ph1[i] = h23;
            float r0 = p0 - __uint_as_float(h01 << 16);
            float r1 = p1 - __uint_as_float(h01 & 0xFFFF0000u);
            float r2 = p2 - __uint_as_float(h23 << 16);
            float r3 = p3 - __uint_as_float(h23 & 0xFFFF0000u);
            pl0[i] = cvt2bf(r1, r0);
            pl1[i] = cvt2bf(r3, r2);
        }
        rs0 += __shfl_xor_sync(0xffffffffu, rs0, 1);
        rs0 += __shfl_xor_sync(0xffffffffu, rs0, 2);
        rs1 += __shfl_xor_sync(0xffffffffu, rs1, 1);
        rs1 += __shfl_xor_sync(0xffffffffu, rs1, 2);
        l0 = l0 * a0 + rs0;
        l1 = l1 * a1 + rs1;

        #pragma unroll
        for (int i = 0; i < 8; i++) {
            o_acc[i][0] *= a0; o_acc[i][1] *= a0;
            o_acc[i][2] *= a1; o_acc[i][3] *= a1;
        }

        // ---- O += Ph*Vh + Ph*Vl + Pl*Vh (accumulator-interleaved) ----
        #pragma unroll
        for (int kk = 0; kk < 4; kk++) {
            uint32_t aH[4] = { ph0[2 * kk], ph1[2 * kk], ph0[2 * kk + 1], ph1[2 * kk + 1] };
            uint32_t aL[4] = { pl0[2 * kk], pl1[2 * kk], pl0[2 * kk + 1], pl1[2 * kk + 1] };
            #pragma unroll
            for (int np = 0; np < 4; np++) {
                uint32_t off = bb + (16u * kk + v_row) * VPITCH + 32u * np + v_col;
                uint32_t h0, h1, h2, h3, e0, e1, e2, e3;
                LDSM4T(h0, h1, h2, h3, sbase + SM_VH + off);
                LDSM4T(e0, e1, e2, e3, sbase + SM_VL + off);
                HMMA(o_acc[2 * np],     aH, h0, h1);
                HMMA(o_acc[2 * np + 1], aH, h2, h3);
                HMMA(o_acc[2 * np],     aL, h0, h1);
                HMMA(o_acc[2 * np + 1], aL, h2, h3);
                HMMA(o_acc[2 * np],     aH, e0, e1);
                HMMA(o_acc[2 * np + 1], aH, e2, e3);
            }
        }

        // ---- STS prefetched tile kt+1 into the other buffer ----
        if (kt + 1 < NTILES) {
            #pragma unroll
            for (int it = 0; it < 8; it++) {
                uint32_t o = nb + (uint32_t)(kr + it * 8) * KPITCH + (uint32_t)kc * 2;
                split_store(smem, SM_KH + o, SM_KL + o, kreg[it]);
            }
            #pragma unroll
            for (int it = 0; it < 4; it++) {
                uint32_t o = nb + (uint32_t)(vr + it * 16) * VPITCH + (uint32_t)vc * 2;
                split_store(smem, SM_VH + o, SM_VL + o, vreg[it]);
            }
        }
        __syncthreads();
    }

    // ================= epilogue =================
    float inv0 = 1.0f / l0, inv1 = 1.0f / l1;
    int row0 = 16 * wid + (lane >> 2);
    int row1 = row0 + 8;
    int colb = 2 * (lane & 3);
    size_t obase = ((size_t)bh * TSEQ + q0);
    #pragma unroll
    for (int i = 0; i < 8; i++) {
        int col = 8 * i + colb;
        *(float2*)(Og + (obase + row0) * TD + col) =
            make_float2(o_acc[i][0] * inv0, o_acc[i][1] * inv0);
        *(float2*)(Og + (obase + row1) * TD + col) =
            make_float2(o_acc[i][2] * inv1, o_acc[i][3] * inv1);
    }
}

extern "C" void kernel_launch(void* const* d_in, const int* in_sizes, int n_in,
                              void* d_out, int out_size)
{
    const float* Q  = (const float*)d_in[0];
    const float* K  = (const float*)d_in[1];
    const float* V  = (const float*)d_in[2];
    const float* Qp = (const float*)d_in[3];
    const float* Kp = (const float*)d_in[4];
    float* O = (float*)d_out;

    cudaFuncSetAttribute(sdpa_mma_ilp_kernel,
                         cudaFuncAttributeMaxDynamicSharedMemorySize, SMEM_TOTAL);

    dim3 grid(TSEQ / BQ, 2 * 16);   // (16, 32)
    sdpa_mma_ilp_kernel<<<grid, NT, SMEM_TOTAL>>>(Q, K, V, Qp, Kp, O);
}

// round 17
// speedup vs baseline: 2.1475x; 1.2809x over previous
#include <cuda_runtime.h>
#include <cuda_fp16.h>
#include <cstdint>

// ---------------- problem constants ----------------
#define TSEQ 2048
#define TD   64
#define BQ   128            // q rows per CTA (32 per warp)
#define BK   64             // kv rows per tile
#define NT   128            // 4 warps
#define NTILES (TSEQ/BK)    // 32

// ---------------- SMEM (bytes, dynamic), double buffered ----------------
// per buffer: KH [64][136]fp16 @0, KL @17408, VH [64][72]fp16 @34816, VL @44032
#define KPITCH 272
#define VPITCH 144
#define SM_KH 0
#define SM_KL 17408
#define SM_VH 34816
#define SM_VL 44032
#define BUFSZ 53248
#define SMEM_TOTAL (2*BUFSZ)        // 106,496 B/CTA -> 2 CTAs/SM = 212,992 B
#define SM_QH 0                     // prologue-only Q-hi staging (128 x 272 B)

// static softmax offset (log2 domain). worst-case |s'| <= 23, realistic <= 12.
#define SOFFS 8.0f

__device__ __forceinline__ uint32_t smem_u32(const void* p) {
    uint32_t a;
    asm("{ .reg .u64 t; cvta.to.shared.u64 t, %1; cvt.u32.u64 %0, t; }" : "=r"(a) : "l"(p));
    return a;
}
__device__ __forceinline__ float ex2(float x) {
    float y;
    asm("ex2.approx.f32 %0, %1;" : "=f"(y) : "f"(x));
    return y;
}
// pack two fp32 -> fp16x2 (e0 -> low half, e1 -> high half)
__device__ __forceinline__ uint32_t cvt2h(float e1, float e0) {
    uint32_t r;
    asm("cvt.rn.f16x2.f32 %0, %1, %2;" : "=r"(r) : "f"(e1), "f"(e0));
    return r;
}

// NOT volatile: pure register dataflow, lets ptxas pipeline/interleave freely.
#define HMMA(d, a, b0, b1)                                                       \
    asm("mma.sync.aligned.m16n8k16.row.col.f32.f16.f16.f32 "                     \
        "{%0,%1,%2,%3}, {%4,%5,%6,%7}, {%8,%9}, {%0,%1,%2,%3};"                  \
        : "+f"((d)[0]), "+f"((d)[1]), "+f"((d)[2]), "+f"((d)[3])                 \
        : "r"((a)[0]), "r"((a)[1]), "r"((a)[2]), "r"((a)[3]), "r"(b0), "r"(b1))

#define LDSM4(r0, r1, r2, r3, addr)                                              \
    asm volatile("ldmatrix.sync.aligned.m8n8.x4.shared.b16 {%0,%1,%2,%3}, [%4];" \
        : "=r"(r0), "=r"(r1), "=r"(r2), "=r"(r3) : "r"(addr))

#define LDSM4T(r0, r1, r2, r3, addr)                                             \
    asm volatile("ldmatrix.sync.aligned.m8n8.x4.trans.shared.b16 {%0,%1,%2,%3}, [%4];" \
        : "=r"(r0), "=r"(r1), "=r"(r2), "=r"(r3) : "r"(addr))

// split one float4 into fp16 hi/lo pairs (8B each)
__device__ __forceinline__ void split_store_h(char* sm, uint32_t off_h, uint32_t off_l,
                                              float4 v) {
    uint32_t h01 = cvt2h(v.y, v.x);
    uint32_t h23 = cvt2h(v.w, v.z);
    float2 fa = __half22float2(*reinterpret_cast<__half2*>(&h01)); // x=lo,y=hi
    float2 fb = __half22float2(*reinterpret_cast<__half2*>(&h23));
    uint32_t l01 = cvt2h(v.y - fa.y, v.x - fa.x);
    uint32_t l23 = cvt2h(v.w - fb.y, v.z - fb.x);
    *(uint2*)(sm + off_h) = make_uint2(h01, h23);
    *(uint2*)(sm + off_l) = make_uint2(l01, l23);
}
// hi-only store (for Q)
__device__ __forceinline__ void store_h(char* sm, uint32_t off, float4 v) {
    *(uint2*)(sm + off) = make_uint2(cvt2h(v.y, v.x), cvt2h(v.w, v.z));
}

__global__ __launch_bounds__(NT, 2)
void sdpa_h2_kernel(const float* __restrict__ Qg,
                    const float* __restrict__ Kg,
                    const float* __restrict__ Vg,
                    const float* __restrict__ Qpg,
                    const float* __restrict__ Kpg,
                    float* __restrict__ Og)
{
    extern __shared__ char smem[];
    const uint32_t sbase = smem_u32(smem);

    const int tid  = threadIdx.x;
    const int wid  = tid >> 5;
    const int lane = tid & 31;

    const int bh = blockIdx.y;
    const int q0 = blockIdx.x * BQ;
    const size_t bh_off = (size_t)bh * TSEQ * TD;
    const float* Kb  = Kg  + bh_off;
    const float* Kpb = Kpg + bh_off;
    const float* Vb  = Vg  + bh_off;

    // ===== prologue: stage Q' scaled by (1/8)*log2e, fp16 hi only =====
    {
        const float* Qb  = Qg  + bh_off;
        const float* Qpb = Qpg + bh_off;
        const float scale = 0.125f * 1.4426950408889634f;
        #pragma unroll
        for (int it = 0; it < 32; it++) {
            int idx4 = tid + it * NT;
            int r = idx4 >> 5;                  // 128 rows, 32 float4/row
            int c = (idx4 & 31) << 2;
            const float* src = (c < TD) ? (Qb + (size_t)(q0 + r) * TD + c)
                                        : (Qpb + (size_t)(q0 + r) * TD + (c - TD));
            float4 v = *(const float4*)src;
            v.x *= scale; v.y *= scale; v.z *= scale; v.w *= scale;
            store_h(smem, SM_QH + (uint32_t)r * KPITCH + (uint32_t)c * 2, v);
        }
    }
    __syncthreads();

    // A-frag row addressing (per 16-row block rb), 32 rows per warp
    const uint32_t a_sub = (lane & 7) + ((lane >> 3) & 1) * 8;
    const uint32_t a_seg = ((uint32_t)(lane >> 4)) * 16;
    uint32_t qh[2][8][4];
    #pragma unroll
    for (int rb = 0; rb < 2; rb++) {
        uint32_t base_r = ((uint32_t)(32 * wid + 16 * rb) + a_sub) * KPITCH + a_seg;
        #pragma unroll
        for (int kk = 0; kk < 8; kk++)
            LDSM4(qh[rb][kk][0], qh[rb][kk][1], qh[rb][kk][2], qh[rb][kk][3],
                  sbase + SM_QH + base_r + (uint32_t)kk * 32);
    }
    __syncthreads();   // Q staging free -> buffers

    // ===== state =====
    float o_acc[2][8][4];
    #pragma unroll
    for (int rb = 0; rb < 2; rb++)
        #pragma unroll
        for (int i = 0; i < 8; i++)
            #pragma unroll
            for (int j = 0; j < 4; j++) o_acc[rb][i][j] = 0.0f;
    float rs[4];
    #pragma unroll
    for (int g = 0; g < 4; g++) rs[g] = 0.0f;

    const uint32_t k_row  = (lane & 7) + ((lane >> 4) & 1) * 8;
    const uint32_t k_kseg = ((lane >> 3) & 1) * 16;
    const uint32_t v_row  = (lane & 7) + ((lane >> 3) & 1) * 8;
    const uint32_t v_col  = ((uint32_t)(lane >> 4)) * 16;

    for (int kt = 0; kt < NTILES; kt++) {
        const int k0 = kt * BK;
        const uint32_t bb = (kt & 1) ? (uint32_t)BUFSZ : 0u;

        // ---- load K'/V tile into buffer bb (hi/lo fp16 split) ----
        // reuse-safety: buffer bb last read at tile kt-2; barrier of kt-1 intervenes.
        #pragma unroll
        for (int it = 0; it < 16; it++) {
            int idx4 = tid + it * NT;
            int r = idx4 >> 5;
            int c = (idx4 & 31) << 2;
            const float* src = (c < TD) ? (Kb + (size_t)(k0 + r) * TD + c)
                                        : (Kpb + (size_t)(k0 + r) * TD + (c - TD));
            float4 v = *(const float4*)src;
            uint32_t o = bb + (uint32_t)r * KPITCH + (uint32_t)c * 2;
            split_store_h(smem, SM_KH + o, SM_KL + o, v);
        }
        #pragma unroll
        for (int it = 0; it < 8; it++) {
            int idx4 = tid + it * NT;
            int r = idx4 >> 4;
            int c = (idx4 & 15) << 2;
            float4 v = *(const float4*)(Vb + (size_t)(k0 + r) * TD + c);
            uint32_t o = bb + (uint32_t)r * VPITCH + (uint32_t)c * 2;
            split_store_h(smem, SM_VH + o, SM_VL + o, v);
        }
        __syncthreads();

        // ---- S = Qh*Kh + Qh*Kl  (32 rows x 64 keys per warp) ----
        float s[2][8][4];
        #pragma unroll
        for (int rb = 0; rb < 2; rb++)
            #pragma unroll
            for (int i = 0; i < 8; i++)
                #pragma unroll
                for (int j = 0; j < 4; j++) s[rb][i][j] = 0.0f;

        #pragma unroll
        for (int kk = 0; kk < 8; kk++) {
            #pragma unroll
            for (int np = 0; np < 4; np++) {
                uint32_t off = bb + (16u * np + k_row) * KPITCH + (uint32_t)kk * 32 + k_kseg;
                uint32_t h0, h1, h2, h3, e0, e1, e2, e3;
                LDSM4(h0, h1, h2, h3, sbase + SM_KH + off);
                LDSM4(e0, e1, e2, e3, sbase + SM_KL + off);
                HMMA(s[0][2 * np],     qh[0][kk], h0, h1);
                HMMA(s[0][2 * np + 1], qh[0][kk], h2, h3);
                HMMA(s[1][2 * np],     qh[1][kk], h0, h1);
                HMMA(s[1][2 * np + 1], qh[1][kk], h2, h3);
                HMMA(s[0][2 * np],     qh[0][kk], e0, e1);
                HMMA(s[0][2 * np + 1], qh[0][kk], e2, e3);
                HMMA(s[1][2 * np],     qh[1][kk], e0, e1);
                HMMA(s[1][2 * np + 1], qh[1][kk], e2, e3);
            }
        }

        // ---- static-max softmax: p = 2^(s - SOFFS); per-element, no shuffles ----
        uint32_t ph0[2][8], ph1[2][8];
        #pragma unroll
        for (int rb = 0; rb < 2; rb++)
            #pragma unroll
            for (int i = 0; i < 8; i++) {
                float p0 = ex2(s[rb][i][0] - SOFFS);
                float p1 = ex2(s[rb][i][1] - SOFFS);
                float p2 = ex2(s[rb][i][2] - SOFFS);
                float p3 = ex2(s[rb][i][3] - SOFFS);
                rs[2 * rb]     += p0 + p1;
                rs[2 * rb + 1] += p2 + p3;
                ph0[rb][i] = cvt2h(p1, p0);
                ph1[rb][i] = cvt2h(p3, p2);
            }

        // ---- O += Ph*Vh + Ph*Vl  (V frags shared across both rbs) ----
        #pragma unroll
        for (int kk2 = 0; kk2 < 4; kk2++) {
            uint32_t aH0[4] = { ph0[0][2*kk2], ph1[0][2*kk2], ph0[0][2*kk2+1], ph1[0][2*kk2+1] };
            uint32_t aH1[4] = { ph0[1][2*kk2], ph1[1][2*kk2], ph0[1][2*kk2+1], ph1[1][2*kk2+1] };
            #pragma unroll
            for (int np = 0; np < 4; np++) {
                uint32_t off = bb + (16u * kk2 + v_row) * VPITCH + 32u * np + v_col;
                uint32_t h0, h1, h2, h3, e0, e1, e2, e3;
                LDSM4T(h0, h1, h2, h3, sbase + SM_VH + off);
                LDSM4T(e0, e1, e2, e3, sbase + SM_VL + off);
                HMMA(o_acc[0][2 * np],     aH0, h0, h1);
                HMMA(o_acc[0][2 * np + 1], aH0, h2, h3);
                HMMA(o_acc[1][2 * np],     aH1, h0, h1);
                HMMA(o_acc[1][2 * np + 1], aH1, h2, h3);
                HMMA(o_acc[0][2 * np],     aH0, e0, e1);
                HMMA(o_acc[0][2 * np + 1], aH0, e2, e3);
                HMMA(o_acc[1][2 * np],     aH1, e0, e1);
                HMMA(o_acc[1][2 * np + 1], aH1, e2, e3);
            }
        }
        // no trailing sync: next tile fills the OTHER buffer; reuse ordered by
        // the next tile's post-load barrier.
    }

    // ================= epilogue: row sums + normalize =================
    #pragma unroll
    for (int g = 0; g < 4; g++) {
        rs[g] += __shfl_xor_sync(0xffffffffu, rs[g], 1);
        rs[g] += __shfl_xor_sync(0xffffffffu, rs[g], 2);
    }
    const int colb = 2 * (lane & 3);
    const size_t obase = ((size_t)bh * TSEQ + q0);
    #pragma unroll
    for (int rb = 0; rb < 2; rb++) {
        float inv0 = 1.0f / rs[2 * rb];
        float inv1 = 1.0f / rs[2 * rb + 1];
        int row0 = 32 * wid + 16 * rb + (lane >> 2);
        int row1 = row0 + 8;
        #pragma unroll
        for (int i = 0; i < 8; i++) {
            int col = 8 * i + colb;
            *(float2*)(Og + (obase + row0) * TD + col) =
                make_float2(o_acc[rb][i][0] * inv0, o_acc[rb][i][1] * inv0);
            *(float2*)(Og + (obase + row1) * TD + col) =
                make_float2(o_acc[rb][i][2] * inv1, o_acc[rb][i][3] * inv1);
        }
    }
}

extern "C" void kernel_launch(void* const* d_in, const int* in_sizes, int n_in,
                              void* d_out, int out_size)
{
    const float* Q  = (const float*)d_in[0];
    const float* K  = (const float*)d_in[1];
    const float* V  = (const float*)d_in[2];
    const float* Qp = (const float*)d_in[3];
    const float* Kp = (const float*)d_in[4];
    float* O = (float*)d_out;

    cudaFuncSetAttribute(sdpa_h2_kernel,
                         cudaFuncAttributeMaxDynamicSharedMemorySize, SMEM_TOTAL);

    dim3 grid(TSEQ / BQ, 2 * 16);   // (16, 32) = 512 CTAs, 2 per SM
    sdpa_h2_kernel<<<grid, NT, SMEM_TOTAL>>>(Q, K, V, Qp, Kp, O);
}